// round 2
// baseline (speedup 1.0000x reference)
#include <cuda_runtime.h>
#include <cuda_bf16.h>
#include <cstddef>

// ---------------------------------------------------------------------------
// FrameLevelPartFeatureExtractor on GB300 — fp32 direct conv, GEMM-style tiles
//
// Pipeline:
//  L1: conv5x5  1->32,  H=1024 W=256, slice 512, double-leaky (slope 1e-4 for <0)
//  L2: conv3x3 32->32,  H=1024 W=256, slice 512
//  P1: maxpool2 -> [2,32,512,128]
//  L3: conv3x3 32->64,  H=512 W=128, slice 32
//  L4: conv3x3 64->64,  H=512 W=128, slice 32
//  P2: maxpool2 -> [2,64,256,64]
//  L5: 1D conv (3 taps, middle kernel row) 64->128, per-row, W=64
//  L6: 1D conv 128->128 -> d_out [2,128,256,64]
// ---------------------------------------------------------------------------

__device__ float g_bufA[2 * 32 * 1024 * 256];   // 64 MB scratch
__device__ float g_bufB[2 * 32 * 1024 * 256];   // 64 MB scratch

__device__ __forceinline__ float dleaky(float y) {
    // leaky_relu(leaky_relu(y, .01), .01) == y>=0 ? y : 1e-4*y
    return (y >= 0.f) ? y : 1e-4f * y;
}

// ---------------------------------------------------------------------------
// L1: 5x5, CIN=1, COUT=32, pad 2, slice 512
// ---------------------------------------------------------------------------
__global__ __launch_bounds__(128)
void conv5_l1(const float* __restrict__ in, const float* __restrict__ wt,
              float* __restrict__ out, int H, int W)
{
    constexpr int TH = 8, TW = 32, SR = TW + 5; // stride 37, conflict-free
    constexpr int SLICE_H = 512, COUT = 32;
    __shared__ float sIn[(TH + 4) * SR];
    __shared__ float sWt[25 * COUT];

    const int b  = blockIdx.z;
    const int h0 = blockIdx.y * TH;
    const int w0 = blockIdx.x * TW;
    const int ss = (h0 / SLICE_H) * SLICE_H;
    const int se = ss + SLICE_H;
    const float* inb = in + (size_t)b * H * W;

    for (int i = threadIdx.x; i < (TH + 4) * (TW + 4); i += 128) {
        int c = i % (TW + 4), r = i / (TW + 4);
        int h = h0 - 2 + r, w = w0 - 2 + c;
        float v = 0.f;
        if (h >= ss && h < se && w >= 0 && w < W) v = inb[(size_t)h * W + w];
        sIn[r * SR + c] = v;
    }
    for (int i = threadIdx.x; i < 25 * COUT; i += 128) {
        int co = i % COUT, k = i / COUT;
        sWt[k * COUT + co] = wt[(size_t)co * 25 + k];
    }
    __syncthreads();

    const int t    = threadIdx.x;
    const int co0  = (t >> 5) * 8;
    const int pg   = t & 31;
    const int prow = pg >> 2;
    const int pc0  = (pg & 3) * 8;

    float acc[8][8];
#pragma unroll
    for (int i = 0; i < 8; ++i)
#pragma unroll
        for (int j = 0; j < 8; ++j) acc[i][j] = 0.f;

#pragma unroll
    for (int dy = 0; dy < 5; ++dy) {
#pragma unroll
        for (int dx = 0; dx < 5; ++dx) {
            const int k = dy * 5 + dx;
            const float4 wa = *(const float4*)(sWt + k * COUT + co0);
            const float4 wb = *(const float4*)(sWt + k * COUT + co0 + 4);
            const float wr[8] = {wa.x, wa.y, wa.z, wa.w, wb.x, wb.y, wb.z, wb.w};
            const float* ip = sIn + (prow + dy) * SR + pc0 + dx;
            float ir[8];
#pragma unroll
            for (int j = 0; j < 8; ++j) ir[j] = ip[j];
#pragma unroll
            for (int i = 0; i < 8; ++i)
#pragma unroll
                for (int j = 0; j < 8; ++j)
                    acc[i][j] = fmaf(wr[i], ir[j], acc[i][j]);
        }
    }

#pragma unroll
    for (int i = 0; i < 8; ++i) {
        float* op = out + (((size_t)b * COUT + co0 + i) * H + (h0 + prow)) * W + w0 + pc0;
#pragma unroll
        for (int j = 0; j < 8; ++j) op[j] = dleaky(acc[i][j]);
    }
}

// ---------------------------------------------------------------------------
// Generic 3x3 conv, pad 1, slice-aware. Block tile: 8h x 32w, all COUT.
// Thread micro-tile: 8 co x 8 px. Weights staged per ci-chunk as [k][co].
// ---------------------------------------------------------------------------
template <int CIN, int COUT, int SLICE_H, int CICH>
__global__ __launch_bounds__((COUT / 8) * 32)
void conv3x3_k(const float* __restrict__ in, const float* __restrict__ wt,
               float* __restrict__ out, int H, int W)
{
    constexpr int TH = 8, TW = 32, SR = TW + 3;  // stride 35 -> conflict-free
    constexpr int NT = (COUT / 8) * 32;
    constexpr int IN_ELEMS = CIN * (TH + 2) * (TW + 2);

    extern __shared__ float smem[];
    float* sIn = smem;                              // CIN*(TH+2)*SR
    float* sWt = smem + CIN * (TH + 2) * SR;        // CICH*9*COUT

    const int b  = blockIdx.z;
    const int h0 = blockIdx.y * TH;
    const int w0 = blockIdx.x * TW;
    const int ss = (h0 / SLICE_H) * SLICE_H;
    const int se = ss + SLICE_H;
    const float* inb = in + (size_t)b * CIN * H * W;

    for (int i = threadIdx.x; i < IN_ELEMS; i += NT) {
        int c  = i % (TW + 2);
        int r  = (i / (TW + 2)) % (TH + 2);
        int ci = i / ((TW + 2) * (TH + 2));
        int h = h0 - 1 + r;
        int w = w0 - 1 + c;
        float v = 0.f;
        if (h >= ss && h < se && w >= 0 && w < W)
            v = inb[((size_t)ci * H + h) * W + w];
        sIn[(ci * (TH + 2) + r) * SR + c] = v;
    }

    const int t    = threadIdx.x;
    const int co0  = (t >> 5) * 8;
    const int pg   = t & 31;
    const int prow = pg >> 2;
    const int pc0  = (pg & 3) * 8;

    float acc[8][8];
#pragma unroll
    for (int i = 0; i < 8; ++i)
#pragma unroll
        for (int j = 0; j < 8; ++j) acc[i][j] = 0.f;

    for (int cc = 0; cc < CIN; cc += CICH) {
        __syncthreads();
        for (int i = t; i < CICH * 9 * COUT; i += NT) {
            int co  = i % COUT;
            int k   = i / COUT;      // cil*9 + kk
            int cil = k / 9, kk = k % 9;
            sWt[k * COUT + co] = wt[((size_t)co * CIN + (cc + cil)) * 9 + kk];
        }
        __syncthreads();

#pragma unroll 1
        for (int cil = 0; cil < CICH; ++cil) {
            const float* sInC = sIn + (size_t)(cc + cil) * (TH + 2) * SR;
            const float* sWk  = sWt + (size_t)cil * 9 * COUT;
#pragma unroll
            for (int dy = 0; dy < 3; ++dy) {
#pragma unroll
                for (int dx = 0; dx < 3; ++dx) {
                    const int k = dy * 3 + dx;
                    const float4 wa = *(const float4*)(sWk + k * COUT + co0);
                    const float4 wb = *(const float4*)(sWk + k * COUT + co0 + 4);
                    const float wr[8] = {wa.x, wa.y, wa.z, wa.w,
                                         wb.x, wb.y, wb.z, wb.w};
                    const float* ip = sInC + (prow + dy) * SR + pc0 + dx;
                    float ir[8];
#pragma unroll
                    for (int j = 0; j < 8; ++j) ir[j] = ip[j];
#pragma unroll
                    for (int i = 0; i < 8; ++i)
#pragma unroll
                        for (int j = 0; j < 8; ++j)
                            acc[i][j] = fmaf(wr[i], ir[j], acc[i][j]);
                }
            }
        }
    }

#pragma unroll
    for (int i = 0; i < 8; ++i) {
        float* op = out + (((size_t)b * COUT + co0 + i) * H + (h0 + prow)) * W + w0 + pc0;
#pragma unroll
        for (int j = 0; j < 8; ++j) op[j] = dleaky(acc[i][j]);
    }
}

// ---------------------------------------------------------------------------
// 1-D conv (3 taps of middle kernel row), per-row independent, W = 64, pad 1.
// Block: 2 rows x 64 cols = 128 px, all COUT=128. Thread: 8 co x 8 px.
// ---------------------------------------------------------------------------
template <int CIN, int COUT, int CICH>
__global__ __launch_bounds__(256)
void conv1d3_k(const float* __restrict__ in, const float* __restrict__ wt,
               float* __restrict__ out, int H, int W)
{
    constexpr int SR = 67;   // W + 3
    constexpr int NT = 256;
    extern __shared__ float smem[];
    float* sIn = smem;                   // CIN*2*SR
    float* sWt = smem + CIN * 2 * SR;    // CICH*3*COUT

    const int R0 = blockIdx.x * 2;

    for (int i = threadIdx.x; i < CIN * 2 * (W + 2); i += NT) {
        int c  = i % (W + 2);
        int r  = (i / (W + 2)) & 1;
        int ci = i / (2 * (W + 2));
        int R = R0 + r;
        int b = R / H, h = R % H;
        int w = c - 1;
        float v = 0.f;
        if (w >= 0 && w < W)
            v = in[(((size_t)b * CIN + ci) * H + h) * W + w];
        sIn[(ci * 2 + r) * SR + c] = v;
    }

    const int t    = threadIdx.x;
    const int co0  = (t >> 4) * 8;
    const int pg   = t & 15;
    const int prow = pg >> 3;
    const int pc0  = (pg & 7) * 8;

    float acc[8][8];
#pragma unroll
    for (int i = 0; i < 8; ++i)
#pragma unroll
        for (int j = 0; j < 8; ++j) acc[i][j] = 0.f;

    for (int cc = 0; cc < CIN; cc += CICH) {
        __syncthreads();
        for (int i = t; i < CICH * 3 * COUT; i += NT) {
            int co  = i % COUT;
            int k   = i / COUT;      // cil*3 + dx
            int cil = k / 3, dx = k % 3;
            // middle kernel row (dy = 1) of wt[co][ci][3][3]
            sWt[k * COUT + co] =
                wt[(((size_t)co * CIN + (cc + cil)) * 3 + 1) * 3 + dx];
        }
        __syncthreads();

#pragma unroll 1
        for (int cil = 0; cil < CICH; ++cil) {
            const float* sInC = sIn + ((size_t)(cc + cil) * 2 + prow) * SR;
            const float* sWk  = sWt + (size_t)cil * 3 * COUT;
#pragma unroll
            for (int dx = 0; dx < 3; ++dx) {
                const float4 wa = *(const float4*)(sWk + dx * COUT + co0);
                const float4 wb = *(const float4*)(sWk + dx * COUT + co0 + 4);
                const float wr[8] = {wa.x, wa.y, wa.z, wa.w,
                                     wb.x, wb.y, wb.z, wb.w};
                const float* ip = sInC + pc0 + dx;
                float ir[8];
#pragma unroll
                for (int j = 0; j < 8; ++j) ir[j] = ip[j];
#pragma unroll
                for (int i = 0; i < 8; ++i)
#pragma unroll
                    for (int j = 0; j < 8; ++j)
                        acc[i][j] = fmaf(wr[i], ir[j], acc[i][j]);
            }
        }
    }

    const int R = R0 + prow;
    const int b = R / H, h = R % H;
#pragma unroll
    for (int i = 0; i < 8; ++i) {
        float* op = out + (((size_t)b * COUT + co0 + i) * H + h) * W + pc0;
#pragma unroll
        for (int j = 0; j < 8; ++j) op[j] = dleaky(acc[i][j]);
    }
}

// ---------------------------------------------------------------------------
// 2x2 max pool, stride 2
// ---------------------------------------------------------------------------
__global__ __launch_bounds__(256)
void maxpool2_k(const float* __restrict__ in, float* __restrict__ out,
                int BC, int H2, int W2)
{
    int idx = blockIdx.x * blockDim.x + threadIdx.x;
    int N = BC * H2 * W2;
    if (idx >= N) return;
    int wo = idx % W2;
    int ho = (idx / W2) % H2;
    int bc = idx / (W2 * H2);
    const float* p = in + (((size_t)bc * (2 * H2)) + 2 * ho) * (2 * W2) + 2 * wo;
    float m0 = fmaxf(p[0], p[1]);
    float m1 = fmaxf(p[2 * W2], p[2 * W2 + 1]);
    out[idx] = fmaxf(m0, m1);
}

// ---------------------------------------------------------------------------
// Host launcher
// ---------------------------------------------------------------------------
static constexpr int SM_L2 = (32 * 10 * 35 + 32 * 9 * 32) * 4;   //  81,664
static constexpr int SM_L3 = (32 * 10 * 35 + 32 * 9 * 64) * 4;   // 118,528
static constexpr int SM_L4 = (64 * 10 * 35 + 16 * 9 * 64) * 4;   // 126,464
static constexpr int SM_L5 = (64 * 2 * 67 + 32 * 3 * 128) * 4;   //  83,456
static constexpr int SM_L6 = (128 * 2 * 67 + 32 * 3 * 128) * 4;  // 117,760

extern "C" void kernel_launch(void* const* d_in, const int* in_sizes, int n_in,
                              void* d_out, int out_size)
{
    const float* x  = (const float*)d_in[0];
    const float* w1 = (const float*)d_in[1];
    const float* w2 = (const float*)d_in[2];
    const float* w3 = (const float*)d_in[3];
    const float* w4 = (const float*)d_in[4];
    const float* w5 = (const float*)d_in[5];
    const float* w6 = (const float*)d_in[6];
    float* out = (float*)d_out;

    float *A, *B;
    cudaGetSymbolAddress((void**)&A, g_bufA);
    cudaGetSymbolAddress((void**)&B, g_bufB);

    cudaFuncSetAttribute(conv3x3_k<32, 32, 512, 32>,
                         cudaFuncAttributeMaxDynamicSharedMemorySize, SM_L2);
    cudaFuncSetAttribute(conv3x3_k<32, 64, 32, 32>,
                         cudaFuncAttributeMaxDynamicSharedMemorySize, SM_L3);
    cudaFuncSetAttribute(conv3x3_k<64, 64, 32, 16>,
                         cudaFuncAttributeMaxDynamicSharedMemorySize, SM_L4);
    cudaFuncSetAttribute(conv1d3_k<64, 128, 32>,
                         cudaFuncAttributeMaxDynamicSharedMemorySize, SM_L5);
    cudaFuncSetAttribute(conv1d3_k<128, 128, 32>,
                         cudaFuncAttributeMaxDynamicSharedMemorySize, SM_L6);

    // L1: x [2,1,1024,256] -> A [2,32,1024,256]
    conv5_l1<<<dim3(8, 128, 2), 128>>>(x, w1, A, 1024, 256);
    // L2: A -> B [2,32,1024,256]
    conv3x3_k<32, 32, 512, 32><<<dim3(8, 128, 2), 128, SM_L2>>>(A, w2, B, 1024, 256);
    // P1: B -> A [2,32,512,128]
    maxpool2_k<<<(2 * 32 * 512 * 128 + 255) / 256, 256>>>(B, A, 64, 512, 128);
    // L3: A -> B [2,64,512,128]
    conv3x3_k<32, 64, 32, 32><<<dim3(4, 64, 2), 256, SM_L3>>>(A, w3, B, 512, 128);
    // L4: B -> A [2,64,512,128]
    conv3x3_k<64, 64, 32, 16><<<dim3(4, 64, 2), 256, SM_L4>>>(B, w4, A, 512, 128);
    // P2: A -> B [2,64,256,64]
    maxpool2_k<<<(2 * 64 * 256 * 64 + 255) / 256, 256>>>(A, B, 128, 256, 64);
    // L5: B -> A [2,128,256,64]
    conv1d3_k<64, 128, 32><<<256, 256, SM_L5>>>(B, w5, A, 256, 64);
    // L6: A -> out [2,128,256,64]
    conv1d3_k<128, 128, 32><<<256, 256, SM_L6>>>(A, w6, out, 256, 64);
}

// round 4
// speedup vs baseline: 1.1694x; 1.1694x over previous
#include <cuda_runtime.h>
#include <cuda_bf16.h>
#include <cstddef>

// ---------------------------------------------------------------------------
// FrameLevelPartFeatureExtractor on GB300 — fp32 direct conv, GEMM-style tiles
// R3: occupancy fix — small weight chunks (CICH=8/16) + reg-capped launch
// bounds so each conv runs 2-4 CTAs/SM (16 warps) instead of 1 CTA (8 warps).
// ---------------------------------------------------------------------------

__device__ float g_bufA[2 * 32 * 1024 * 256];   // 64 MB scratch
__device__ float g_bufB[2 * 32 * 1024 * 256];   // 64 MB scratch

__device__ __forceinline__ float dleaky(float y) {
    // leaky_relu(leaky_relu(y, .01), .01) == y>=0 ? y : 1e-4*y
    return (y >= 0.f) ? y : 1e-4f * y;
}

// ---------------------------------------------------------------------------
// L1: 5x5, CIN=1, COUT=32, pad 2, slice 512
// ---------------------------------------------------------------------------
__global__ __launch_bounds__(128, 4)
void conv5_l1(const float* __restrict__ in, const float* __restrict__ wt,
              float* __restrict__ out, int H, int W)
{
    constexpr int TH = 8, TW = 32, SR = TW + 5; // stride 37, conflict-free
    constexpr int SLICE_H = 512, COUT = 32;
    __shared__ float sIn[(TH + 4) * SR];
    __shared__ float sWt[25 * COUT];

    const int b  = blockIdx.z;
    const int h0 = blockIdx.y * TH;
    const int w0 = blockIdx.x * TW;
    const int ss = (h0 / SLICE_H) * SLICE_H;
    const int se = ss + SLICE_H;
    const float* inb = in + (size_t)b * H * W;

    for (int i = threadIdx.x; i < (TH + 4) * (TW + 4); i += 128) {
        int c = i % (TW + 4), r = i / (TW + 4);
        int h = h0 - 2 + r, w = w0 - 2 + c;
        float v = 0.f;
        if (h >= ss && h < se && w >= 0 && w < W) v = inb[(size_t)h * W + w];
        sIn[r * SR + c] = v;
    }
    for (int i = threadIdx.x; i < 25 * COUT; i += 128) {
        int co = i % COUT, k = i / COUT;
        sWt[k * COUT + co] = wt[(size_t)co * 25 + k];
    }
    __syncthreads();

    const int t    = threadIdx.x;
    const int co0  = (t >> 5) * 8;
    const int pg   = t & 31;
    const int prow = pg >> 2;
    const int pc0  = (pg & 3) * 8;

    float acc[8][8];
#pragma unroll
    for (int i = 0; i < 8; ++i)
#pragma unroll
        for (int j = 0; j < 8; ++j) acc[i][j] = 0.f;

#pragma unroll
    for (int dy = 0; dy < 5; ++dy) {
#pragma unroll
        for (int dx = 0; dx < 5; ++dx) {
            const int k = dy * 5 + dx;
            const float4 wa = *(const float4*)(sWt + k * COUT + co0);
            const float4 wb = *(const float4*)(sWt + k * COUT + co0 + 4);
            const float wr[8] = {wa.x, wa.y, wa.z, wa.w, wb.x, wb.y, wb.z, wb.w};
            const float* ip = sIn + (prow + dy) * SR + pc0 + dx;
            float ir[8];
#pragma unroll
            for (int j = 0; j < 8; ++j) ir[j] = ip[j];
#pragma unroll
            for (int i = 0; i < 8; ++i)
#pragma unroll
                for (int j = 0; j < 8; ++j)
                    acc[i][j] = fmaf(wr[i], ir[j], acc[i][j]);
        }
    }

#pragma unroll
    for (int i = 0; i < 8; ++i) {
        float* op = out + (((size_t)b * COUT + co0 + i) * H + (h0 + prow)) * W + w0 + pc0;
#pragma unroll
        for (int j = 0; j < 8; ++j) op[j] = dleaky(acc[i][j]);
    }
}

// ---------------------------------------------------------------------------
// Generic 3x3 conv, pad 1, slice-aware. Block tile: 8h x 32w, all COUT.
// Thread micro-tile: 8 co x 8 px. Weights staged per ci-chunk as [k][co].
// ---------------------------------------------------------------------------
template <int CIN, int COUT, int SLICE_H, int CICH>
__global__ __launch_bounds__((COUT / 8) * 32, (COUT == 32) ? 4 : 2)
void conv3x3_k(const float* __restrict__ in, const float* __restrict__ wt,
               float* __restrict__ out, int H, int W)
{
    constexpr int TH = 8, TW = 32, SR = TW + 3;  // stride 35 -> conflict-free
    constexpr int NT = (COUT / 8) * 32;
    constexpr int IN_ELEMS = CIN * (TH + 2) * (TW + 2);

    extern __shared__ float smem[];
    float* sIn = smem;                              // CIN*(TH+2)*SR
    float* sWt = smem + CIN * (TH + 2) * SR;        // CICH*9*COUT

    const int b  = blockIdx.z;
    const int h0 = blockIdx.y * TH;
    const int w0 = blockIdx.x * TW;
    const int ss = (h0 / SLICE_H) * SLICE_H;
    const int se = ss + SLICE_H;
    const float* inb = in + (size_t)b * CIN * H * W;

    for (int i = threadIdx.x; i < IN_ELEMS; i += NT) {
        int c  = i % (TW + 2);
        int r  = (i / (TW + 2)) % (TH + 2);
        int ci = i / ((TW + 2) * (TH + 2));
        int h = h0 - 1 + r;
        int w = w0 - 1 + c;
        float v = 0.f;
        if (h >= ss && h < se && w >= 0 && w < W)
            v = inb[((size_t)ci * H + h) * W + w];
        sIn[(ci * (TH + 2) + r) * SR + c] = v;
    }

    const int t    = threadIdx.x;
    const int co0  = (t >> 5) * 8;
    const int pg   = t & 31;
    const int prow = pg >> 2;
    const int pc0  = (pg & 3) * 8;

    float acc[8][8];
#pragma unroll
    for (int i = 0; i < 8; ++i)
#pragma unroll
        for (int j = 0; j < 8; ++j) acc[i][j] = 0.f;

    for (int cc = 0; cc < CIN; cc += CICH) {
        __syncthreads();
        for (int i = t; i < CICH * 9 * COUT; i += NT) {
            int co  = i % COUT;
            int k   = i / COUT;      // cil*9 + kk
            int cil = k / 9, kk = k % 9;
            sWt[k * COUT + co] = wt[((size_t)co * CIN + (cc + cil)) * 9 + kk];
        }
        __syncthreads();

#pragma unroll 1
        for (int cil = 0; cil < CICH; ++cil) {
            const float* sInC = sIn + (size_t)(cc + cil) * (TH + 2) * SR;
            const float* sWk  = sWt + (size_t)cil * 9 * COUT;
#pragma unroll
            for (int dy = 0; dy < 3; ++dy) {
#pragma unroll
                for (int dx = 0; dx < 3; ++dx) {
                    const int k = dy * 3 + dx;
                    const float4 wa = *(const float4*)(sWk + k * COUT + co0);
                    const float4 wb = *(const float4*)(sWk + k * COUT + co0 + 4);
                    const float wr[8] = {wa.x, wa.y, wa.z, wa.w,
                                         wb.x, wb.y, wb.z, wb.w};
                    const float* ip = sInC + (prow + dy) * SR + pc0 + dx;
                    float ir[8];
#pragma unroll
                    for (int j = 0; j < 8; ++j) ir[j] = ip[j];
#pragma unroll
                    for (int i = 0; i < 8; ++i)
#pragma unroll
                        for (int j = 0; j < 8; ++j)
                            acc[i][j] = fmaf(wr[i], ir[j], acc[i][j]);
                }
            }
        }
    }

#pragma unroll
    for (int i = 0; i < 8; ++i) {
        float* op = out + (((size_t)b * COUT + co0 + i) * H + (h0 + prow)) * W + w0 + pc0;
#pragma unroll
        for (int j = 0; j < 8; ++j) op[j] = dleaky(acc[i][j]);
    }
}

// ---------------------------------------------------------------------------
// 1-D conv (3 taps of middle kernel row), per-row independent, W = 64, pad 1.
// Block: 2 rows x 64 cols = 128 px, all COUT=128. Thread: 8 co x 8 px.
// ---------------------------------------------------------------------------
template <int CIN, int COUT, int CICH>
__global__ __launch_bounds__(256, 2)
void conv1d3_k(const float* __restrict__ in, const float* __restrict__ wt,
               float* __restrict__ out, int H, int W)
{
    constexpr int SR = 67;   // W + 3
    constexpr int NT = 256;
    extern __shared__ float smem[];
    float* sIn = smem;                   // CIN*2*SR
    float* sWt = smem + CIN * 2 * SR;    // CICH*3*COUT

    const int R0 = blockIdx.x * 2;

    for (int i = threadIdx.x; i < CIN * 2 * (W + 2); i += NT) {
        int c  = i % (W + 2);
        int r  = (i / (W + 2)) & 1;
        int ci = i / (2 * (W + 2));
        int R = R0 + r;
        int b = R / H, h = R % H;
        int w = c - 1;
        float v = 0.f;
        if (w >= 0 && w < W)
            v = in[(((size_t)b * CIN + ci) * H + h) * W + w];
        sIn[(ci * 2 + r) * SR + c] = v;
    }

    const int t    = threadIdx.x;
    const int co0  = (t >> 4) * 8;
    const int pg   = t & 15;
    const int prow = pg >> 3;
    const int pc0  = (pg & 7) * 8;

    float acc[8][8];
#pragma unroll
    for (int i = 0; i < 8; ++i)
#pragma unroll
        for (int j = 0; j < 8; ++j) acc[i][j] = 0.f;

    for (int cc = 0; cc < CIN; cc += CICH) {
        __syncthreads();
        for (int i = t; i < CICH * 3 * COUT; i += NT) {
            int co  = i % COUT;
            int k   = i / COUT;      // cil*3 + dx
            int cil = k / 3, dx = k % 3;
            // middle kernel row (dy = 1) of wt[co][ci][3][3]
            sWt[k * COUT + co] =
                wt[(((size_t)co * CIN + (cc + cil)) * 3 + 1) * 3 + dx];
        }
        __syncthreads();

#pragma unroll 1
        for (int cil = 0; cil < CICH; ++cil) {
            const float* sInC = sIn + ((size_t)(cc + cil) * 2 + prow) * SR;
            const float* sWk  = sWt + (size_t)cil * 3 * COUT;
#pragma unroll
            for (int dx = 0; dx < 3; ++dx) {
                const float4 wa = *(const float4*)(sWk + dx * COUT + co0);
                const float4 wb = *(const float4*)(sWk + dx * COUT + co0 + 4);
                const float wr[8] = {wa.x, wa.y, wa.z, wa.w,
                                     wb.x, wb.y, wb.z, wb.w};
                const float* ip = sInC + pc0 + dx;
                float ir[8];
#pragma unroll
                for (int j = 0; j < 8; ++j) ir[j] = ip[j];
#pragma unroll
                for (int i = 0; i < 8; ++i)
#pragma unroll
                    for (int j = 0; j < 8; ++j)
                        acc[i][j] = fmaf(wr[i], ir[j], acc[i][j]);
            }
        }
    }

    const int R = R0 + prow;
    const int b = R / H, h = R % H;
#pragma unroll
    for (int i = 0; i < 8; ++i) {
        float* op = out + (((size_t)b * COUT + co0 + i) * H + h) * W + pc0;
#pragma unroll
        for (int j = 0; j < 8; ++j) op[j] = dleaky(acc[i][j]);
    }
}

// ---------------------------------------------------------------------------
// 2x2 max pool, stride 2
// ---------------------------------------------------------------------------
__global__ __launch_bounds__(256)
void maxpool2_k(const float* __restrict__ in, float* __restrict__ out,
                int BC, int H2, int W2)
{
    int idx = blockIdx.x * blockDim.x + threadIdx.x;
    int N = BC * H2 * W2;
    if (idx >= N) return;
    int wo = idx % W2;
    int ho = (idx / W2) % H2;
    int bc = idx / (W2 * H2);
    const float* p = in + (((size_t)bc * (2 * H2)) + 2 * ho) * (2 * W2) + 2 * wo;
    float m0 = fmaxf(p[0], p[1]);
    float m1 = fmaxf(p[2 * W2], p[2 * W2 + 1]);
    out[idx] = fmaxf(m0, m1);
}

// ---------------------------------------------------------------------------
// Host launcher
//   Weight chunk CICH shrunk so smem allows 2-4 CTAs/SM:
//   L2: 54.0KB -> 4 CTAs (128-thr blocks)   L3: 63.2KB -> 2 CTAs (reg-lim)
//   L4: 108.0KB -> 2 CTAs                   L5: 58.9KB / L6: 93.2KB -> 2 CTAs
// ---------------------------------------------------------------------------
static constexpr int SM_L2 = (32 * 10 * 35 + 8 * 9 * 32) * 4;    //  54,016
static constexpr int SM_L3 = (32 * 10 * 35 + 8 * 9 * 64) * 4;    //  63,232
static constexpr int SM_L4 = (64 * 10 * 35 + 8 * 9 * 64) * 4;    // 108,032
static constexpr int SM_L5 = (64 * 2 * 67 + 16 * 3 * 128) * 4;   //  58,880
static constexpr int SM_L6 = (128 * 2 * 67 + 16 * 3 * 128) * 4;  //  93,184

extern "C" void kernel_launch(void* const* d_in, const int* in_sizes, int n_in,
                              void* d_out, int out_size)
{
    const float* x  = (const float*)d_in[0];
    const float* w1 = (const float*)d_in[1];
    const float* w2 = (const float*)d_in[2];
    const float* w3 = (const float*)d_in[3];
    const float* w4 = (const float*)d_in[4];
    const float* w5 = (const float*)d_in[5];
    const float* w6 = (const float*)d_in[6];
    float* out = (float*)d_out;

    float *A, *B;
    cudaGetSymbolAddress((void**)&A, g_bufA);
    cudaGetSymbolAddress((void**)&B, g_bufB);

    cudaFuncSetAttribute(conv3x3_k<32, 32, 512, 8>,
                         cudaFuncAttributeMaxDynamicSharedMemorySize, SM_L2);
    cudaFuncSetAttribute(conv3x3_k<32, 64, 32, 8>,
                         cudaFuncAttributeMaxDynamicSharedMemorySize, SM_L3);
    cudaFuncSetAttribute(conv3x3_k<64, 64, 32, 8>,
                         cudaFuncAttributeMaxDynamicSharedMemorySize, SM_L4);
    cudaFuncSetAttribute(conv1d3_k<64, 128, 16>,
                         cudaFuncAttributeMaxDynamicSharedMemorySize, SM_L5);
    cudaFuncSetAttribute(conv1d3_k<128, 128, 16>,
                         cudaFuncAttributeMaxDynamicSharedMemorySize, SM_L6);

    // L1: x [2,1,1024,256] -> A [2,32,1024,256]
    conv5_l1<<<dim3(8, 128, 2), 128>>>(x, w1, A, 1024, 256);
    // L2: A -> B [2,32,1024,256]
    conv3x3_k<32, 32, 512, 8><<<dim3(8, 128, 2), 128, SM_L2>>>(A, w2, B, 1024, 256);
    // P1: B -> A [2,32,512,128]
    maxpool2_k<<<(2 * 32 * 512 * 128 + 255) / 256, 256>>>(B, A, 64, 512, 128);
    // L3: A -> B [2,64,512,128]
    conv3x3_k<32, 64, 32, 8><<<dim3(4, 64, 2), 256, SM_L3>>>(A, w3, B, 512, 128);
    // L4: B -> A [2,64,512,128]
    conv3x3_k<64, 64, 32, 8><<<dim3(4, 64, 2), 256, SM_L4>>>(B, w4, A, 512, 128);
    // P2: A -> B [2,64,256,64]
    maxpool2_k<<<(2 * 64 * 256 * 64 + 255) / 256, 256>>>(A, B, 128, 256, 64);
    // L5: B -> A [2,128,256,64]
    conv1d3_k<64, 128, 16><<<256, 256, SM_L5>>>(B, w5, A, 256, 64);
    // L6: A -> out [2,128,256,64]
    conv1d3_k<128, 128, 16><<<256, 256, SM_L6>>>(A, w6, out, 256, 64);
}

// round 5
// speedup vs baseline: 1.3184x; 1.1274x over previous
#include <cuda_runtime.h>
#include <cuda_bf16.h>
#include <cstddef>

// ---------------------------------------------------------------------------
// FrameLevelPartFeatureExtractor on GB300 — R5: packed fp32x2 FFMA convs.
//  * conv3x3 / conv1d inner loops use fma.rn.f32x2 with co-pair packing:
//      - weights [k][co] in smem -> ulonglong2 LDS.128 = two ready (co,co+1) pairs
//      - inputs register-cached per row (3x LDS.128, 16B-aligned rows) + splats
//  * 2x flops per issue slot vs scalar FFMA.
// ---------------------------------------------------------------------------

__device__ float g_bufA[2 * 32 * 1024 * 256];   // 64 MB scratch
__device__ float g_bufB[2 * 32 * 1024 * 256];   // 64 MB scratch

__device__ __forceinline__ float dleaky(float y) {
    // leaky_relu(leaky_relu(y, .01), .01) == y>=0 ? y : 1e-4*y
    return (y >= 0.f) ? y : 1e-4f * y;
}

__device__ __forceinline__ unsigned long long splat2(float v) {
    unsigned long long r;
    asm("mov.b64 %0, {%1, %1};" : "=l"(r) : "f"(v));
    return r;
}
__device__ __forceinline__ void fma2(unsigned long long& d,
                                     unsigned long long a,
                                     unsigned long long b) {
    asm("fma.rn.f32x2 %0, %1, %2, %3;" : "=l"(d) : "l"(a), "l"(b), "l"(d));
}
__device__ __forceinline__ void unpack2(float& lo, float& hi, unsigned long long v) {
    asm("mov.b64 {%0, %1}, %2;" : "=f"(lo), "=f"(hi) : "l"(v));
}

// ---------------------------------------------------------------------------
// L1: 5x5, CIN=1, COUT=32, pad 2, slice 512 (scalar; tiny layer)
// ---------------------------------------------------------------------------
__global__ __launch_bounds__(128, 4)
void conv5_l1(const float* __restrict__ in, const float* __restrict__ wt,
              float* __restrict__ out, int H, int W)
{
    constexpr int TH = 8, TW = 32, SR = TW + 5;
    constexpr int SLICE_H = 512, COUT = 32;
    __shared__ float sIn[(TH + 4) * SR];
    __shared__ float sWt[25 * COUT];

    const int b  = blockIdx.z;
    const int h0 = blockIdx.y * TH;
    const int w0 = blockIdx.x * TW;
    const int ss = (h0 / SLICE_H) * SLICE_H;
    const int se = ss + SLICE_H;
    const float* inb = in + (size_t)b * H * W;

    for (int i = threadIdx.x; i < (TH + 4) * (TW + 4); i += 128) {
        int c = i % (TW + 4), r = i / (TW + 4);
        int h = h0 - 2 + r, w = w0 - 2 + c;
        float v = 0.f;
        if (h >= ss && h < se && w >= 0 && w < W) v = inb[(size_t)h * W + w];
        sIn[r * SR + c] = v;
    }
    for (int i = threadIdx.x; i < 25 * COUT; i += 128) {
        int co = i % COUT, k = i / COUT;
        sWt[k * COUT + co] = wt[(size_t)co * 25 + k];
    }
    __syncthreads();

    const int t    = threadIdx.x;
    const int co0  = (t >> 5) * 8;
    const int pg   = t & 31;
    const int prow = pg >> 2;
    const int pc0  = (pg & 3) * 8;

    float acc[8][8];
#pragma unroll
    for (int i = 0; i < 8; ++i)
#pragma unroll
        for (int j = 0; j < 8; ++j) acc[i][j] = 0.f;

#pragma unroll
    for (int dy = 0; dy < 5; ++dy) {
#pragma unroll
        for (int dx = 0; dx < 5; ++dx) {
            const int k = dy * 5 + dx;
            const float4 wa = *(const float4*)(sWt + k * COUT + co0);
            const float4 wb = *(const float4*)(sWt + k * COUT + co0 + 4);
            const float wr[8] = {wa.x, wa.y, wa.z, wa.w, wb.x, wb.y, wb.z, wb.w};
            const float* ip = sIn + (prow + dy) * SR + pc0 + dx;
            float ir[8];
#pragma unroll
            for (int j = 0; j < 8; ++j) ir[j] = ip[j];
#pragma unroll
            for (int i = 0; i < 8; ++i)
#pragma unroll
                for (int j = 0; j < 8; ++j)
                    acc[i][j] = fmaf(wr[i], ir[j], acc[i][j]);
        }
    }

#pragma unroll
    for (int i = 0; i < 8; ++i) {
        float* op = out + (((size_t)b * COUT + co0 + i) * H + (h0 + prow)) * W + w0 + pc0;
#pragma unroll
        for (int j = 0; j < 8; ++j) op[j] = dleaky(acc[i][j]);
    }
}

// ---------------------------------------------------------------------------
// 3x3 conv, pad 1, slice-aware, fp32x2 co-pair packed.
// Block tile: 8h x 32w, all COUT. Thread: 4 co-pairs x 8 px.
// ---------------------------------------------------------------------------
template <int CIN, int COUT, int SLICE_H, int CICH>
__global__ __launch_bounds__((COUT / 8) * 32, (COUT == 32) ? 4 : 2)
void conv3x3_f2(const float* __restrict__ in, const float* __restrict__ wt,
                float* __restrict__ out, int H, int W)
{
    constexpr int TH = 8, TW = 32, SR = 36;      // rows 144B -> 16B aligned
    constexpr int NT = (COUT / 8) * 32;
    constexpr int IN_ELEMS = CIN * (TH + 2) * (TW + 2);

    extern __shared__ float smem[];
    float* sIn = smem;                              // CIN*(TH+2)*SR
    float* sWt = smem + CIN * (TH + 2) * SR;        // CICH*9*COUT

    const int b  = blockIdx.z;
    const int h0 = blockIdx.y * TH;
    const int w0 = blockIdx.x * TW;
    const int ss = (h0 / SLICE_H) * SLICE_H;
    const int se = ss + SLICE_H;
    const float* inb = in + (size_t)b * CIN * H * W;

    for (int i = threadIdx.x; i < IN_ELEMS; i += NT) {
        int c  = i % (TW + 2);
        int r  = (i / (TW + 2)) % (TH + 2);
        int ci = i / ((TW + 2) * (TH + 2));
        int h = h0 - 1 + r;
        int w = w0 - 1 + c;
        float v = 0.f;
        if (h >= ss && h < se && w >= 0 && w < W)
            v = inb[((size_t)ci * H + h) * W + w];
        sIn[(ci * (TH + 2) + r) * SR + c] = v;
    }

    const int t    = threadIdx.x;
    const int co0  = (t >> 5) * 8;
    const int pg   = t & 31;
    const int prow = pg >> 2;
    const int pc0  = (pg & 3) * 8;

    unsigned long long acc[4][8];
#pragma unroll
    for (int i = 0; i < 4; ++i)
#pragma unroll
        for (int j = 0; j < 8; ++j) acc[i][j] = 0ull;

    for (int cc = 0; cc < CIN; cc += CICH) {
        __syncthreads();
        for (int i = t; i < CICH * 9 * COUT; i += NT) {
            int co  = i % COUT;
            int k   = i / COUT;      // cil*9 + kk
            int cil = k / 9, kk = k % 9;
            sWt[k * COUT + co] = wt[((size_t)co * CIN + (cc + cil)) * 9 + kk];
        }
        __syncthreads();

#pragma unroll 1
        for (int cil = 0; cil < CICH; ++cil) {
            const float* sInC = sIn + (size_t)(cc + cil) * (TH + 2) * SR;
            const float* sWk  = sWt + (size_t)cil * 9 * COUT;
#pragma unroll
            for (int dy = 0; dy < 3; ++dy) {
                const float* rp = sInC + (prow + dy) * SR + pc0;
                const float4 ra = *(const float4*)(rp);
                const float4 rb = *(const float4*)(rp + 4);
                const float4 rc = *(const float4*)(rp + 8);
                unsigned long long s[10];
                s[0] = splat2(ra.x); s[1] = splat2(ra.y);
                s[2] = splat2(ra.z); s[3] = splat2(ra.w);
                s[4] = splat2(rb.x); s[5] = splat2(rb.y);
                s[6] = splat2(rb.z); s[7] = splat2(rb.w);
                s[8] = splat2(rc.x); s[9] = splat2(rc.y);
#pragma unroll
                for (int dx = 0; dx < 3; ++dx) {
                    const int k = dy * 3 + dx;
                    const ulonglong2 wA = *(const ulonglong2*)(sWk + k * COUT + co0);
                    const ulonglong2 wB = *(const ulonglong2*)(sWk + k * COUT + co0 + 4);
#pragma unroll
                    for (int j = 0; j < 8; ++j) {
                        fma2(acc[0][j], wA.x, s[dx + j]);
                        fma2(acc[1][j], wA.y, s[dx + j]);
                        fma2(acc[2][j], wB.x, s[dx + j]);
                        fma2(acc[3][j], wB.y, s[dx + j]);
                    }
                }
            }
        }
    }

#pragma unroll
    for (int i = 0; i < 4; ++i) {
        float* opL = out + (((size_t)b * COUT + co0 + 2 * i) * H + (h0 + prow)) * W + w0 + pc0;
        float* opH = opL + (size_t)H * W;
#pragma unroll
        for (int j = 0; j < 8; ++j) {
            float lo, hi;
            unpack2(lo, hi, acc[i][j]);
            opL[j] = dleaky(lo);
            opH[j] = dleaky(hi);
        }
    }
}

// ---------------------------------------------------------------------------
// 1-D conv (3 taps, middle kernel row), per-row, W=64, pad 1, fp32x2 packed.
// Block: 2 rows x 64 cols, all COUT=128. Thread: 4 co-pairs x 8 px.
// ---------------------------------------------------------------------------
template <int CIN, int COUT, int CICH>
__global__ __launch_bounds__(256, 2)
void conv1d3_f2(const float* __restrict__ in, const float* __restrict__ wt,
                float* __restrict__ out, int H, int W)
{
    constexpr int SR = 68;   // 272B rows -> 16B aligned
    constexpr int NT = 256;
    extern __shared__ float smem[];
    float* sIn = smem;                   // CIN*2*SR
    float* sWt = smem + CIN * 2 * SR;    // CICH*3*COUT

    const int R0 = blockIdx.x * 2;

    for (int i = threadIdx.x; i < CIN * 2 * (W + 2); i += NT) {
        int c  = i % (W + 2);
        int r  = (i / (W + 2)) & 1;
        int ci = i / (2 * (W + 2));
        int R = R0 + r;
        int b = R / H, h = R % H;
        int w = c - 1;
        float v = 0.f;
        if (w >= 0 && w < W)
            v = in[(((size_t)b * CIN + ci) * H + h) * W + w];
        sIn[(ci * 2 + r) * SR + c] = v;
    }

    const int t    = threadIdx.x;
    const int co0  = (t >> 4) * 8;
    const int pg   = t & 15;
    const int prow = pg >> 3;
    const int pc0  = (pg & 7) * 8;

    unsigned long long acc[4][8];
#pragma unroll
    for (int i = 0; i < 4; ++i)
#pragma unroll
        for (int j = 0; j < 8; ++j) acc[i][j] = 0ull;

    for (int cc = 0; cc < CIN; cc += CICH) {
        __syncthreads();
        for (int i = t; i < CICH * 3 * COUT; i += NT) {
            int co  = i % COUT;
            int k   = i / COUT;      // cil*3 + dx
            int cil = k / 3, dx = k % 3;
            // middle kernel row (dy = 1) of wt[co][ci][3][3]
            sWt[k * COUT + co] =
                wt[(((size_t)co * CIN + (cc + cil)) * 3 + 1) * 3 + dx];
        }
        __syncthreads();

#pragma unroll 1
        for (int cil = 0; cil < CICH; ++cil) {
            const float* rp = sIn + ((size_t)(cc + cil) * 2 + prow) * SR + pc0;
            const float* sWk = sWt + (size_t)cil * 3 * COUT;
            const float4 ra = *(const float4*)(rp);
            const float4 rb = *(const float4*)(rp + 4);
            const float4 rc = *(const float4*)(rp + 8);
            unsigned long long s[10];
            s[0] = splat2(ra.x); s[1] = splat2(ra.y);
            s[2] = splat2(ra.z); s[3] = splat2(ra.w);
            s[4] = splat2(rb.x); s[5] = splat2(rb.y);
            s[6] = splat2(rb.z); s[7] = splat2(rb.w);
            s[8] = splat2(rc.x); s[9] = splat2(rc.y);
#pragma unroll
            for (int dx = 0; dx < 3; ++dx) {
                const ulonglong2 wA = *(const ulonglong2*)(sWk + dx * COUT + co0);
                const ulonglong2 wB = *(const ulonglong2*)(sWk + dx * COUT + co0 + 4);
#pragma unroll
                for (int j = 0; j < 8; ++j) {
                    fma2(acc[0][j], wA.x, s[dx + j]);
                    fma2(acc[1][j], wA.y, s[dx + j]);
                    fma2(acc[2][j], wB.x, s[dx + j]);
                    fma2(acc[3][j], wB.y, s[dx + j]);
                }
            }
        }
    }

    const int R = R0 + prow;
    const int b = R / H, h = R % H;
#pragma unroll
    for (int i = 0; i < 4; ++i) {
        float* opL = out + (((size_t)b * COUT + co0 + 2 * i) * H + h) * W + pc0;
        float* opH = opL + (size_t)H * W;
#pragma unroll
        for (int j = 0; j < 8; ++j) {
            float lo, hi;
            unpack2(lo, hi, acc[i][j]);
            opL[j] = dleaky(lo);
            opH[j] = dleaky(hi);
        }
    }
}

// ---------------------------------------------------------------------------
// 2x2 max pool, stride 2
// ---------------------------------------------------------------------------
__global__ __launch_bounds__(256)
void maxpool2_k(const float* __restrict__ in, float* __restrict__ out,
                int BC, int H2, int W2)
{
    int idx = blockIdx.x * blockDim.x + threadIdx.x;
    int N = BC * H2 * W2;
    if (idx >= N) return;
    int wo = idx % W2;
    int ho = (idx / W2) % H2;
    int bc = idx / (W2 * H2);
    const float* p = in + (((size_t)bc * (2 * H2)) + 2 * ho) * (2 * W2) + 2 * wo;
    float m0 = fmaxf(p[0], p[1]);
    float m1 = fmaxf(p[2 * W2], p[2 * W2 + 1]);
    out[idx] = fmaxf(m0, m1);
}

// ---------------------------------------------------------------------------
// Host launcher
// ---------------------------------------------------------------------------
static constexpr int SM_L2 = (32 * 10 * 36 + 8 * 9 * 32) * 4;    //  55,296
static constexpr int SM_L3 = (32 * 10 * 36 + 8 * 9 * 64) * 4;    //  64,512
static constexpr int SM_L4 = (64 * 10 * 36 + 8 * 9 * 64) * 4;    // 110,592
static constexpr int SM_L5 = (64 * 2 * 68 + 16 * 3 * 128) * 4;   //  59,392
static constexpr int SM_L6 = (128 * 2 * 68 + 16 * 3 * 128) * 4;  //  94,208

extern "C" void kernel_launch(void* const* d_in, const int* in_sizes, int n_in,
                              void* d_out, int out_size)
{
    const float* x  = (const float*)d_in[0];
    const float* w1 = (const float*)d_in[1];
    const float* w2 = (const float*)d_in[2];
    const float* w3 = (const float*)d_in[3];
    const float* w4 = (const float*)d_in[4];
    const float* w5 = (const float*)d_in[5];
    const float* w6 = (const float*)d_in[6];
    float* out = (float*)d_out;

    float *A, *B;
    cudaGetSymbolAddress((void**)&A, g_bufA);
    cudaGetSymbolAddress((void**)&B, g_bufB);

    cudaFuncSetAttribute(conv3x3_f2<32, 32, 512, 8>,
                         cudaFuncAttributeMaxDynamicSharedMemorySize, SM_L2);
    cudaFuncSetAttribute(conv3x3_f2<32, 64, 32, 8>,
                         cudaFuncAttributeMaxDynamicSharedMemorySize, SM_L3);
    cudaFuncSetAttribute(conv3x3_f2<64, 64, 32, 8>,
                         cudaFuncAttributeMaxDynamicSharedMemorySize, SM_L4);
    cudaFuncSetAttribute(conv1d3_f2<64, 128, 16>,
                         cudaFuncAttributeMaxDynamicSharedMemorySize, SM_L5);
    cudaFuncSetAttribute(conv1d3_f2<128, 128, 16>,
                         cudaFuncAttributeMaxDynamicSharedMemorySize, SM_L6);

    // L1: x [2,1,1024,256] -> A [2,32,1024,256]
    conv5_l1<<<dim3(8, 128, 2), 128>>>(x, w1, A, 1024, 256);
    // L2: A -> B [2,32,1024,256]
    conv3x3_f2<32, 32, 512, 8><<<dim3(8, 128, 2), 128, SM_L2>>>(A, w2, B, 1024, 256);
    // P1: B -> A [2,32,512,128]
    maxpool2_k<<<(2 * 32 * 512 * 128 + 255) / 256, 256>>>(B, A, 64, 512, 128);
    // L3: A -> B [2,64,512,128]
    conv3x3_f2<32, 64, 32, 8><<<dim3(4, 64, 2), 256, SM_L3>>>(A, w3, B, 512, 128);
    // L4: B -> A [2,64,512,128]
    conv3x3_f2<64, 64, 32, 8><<<dim3(4, 64, 2), 256, SM_L4>>>(B, w4, A, 512, 128);
    // P2: A -> B [2,64,256,64]
    maxpool2_k<<<(2 * 64 * 256 * 64 + 255) / 256, 256>>>(A, B, 128, 256, 64);
    // L5: B -> A [2,128,256,64]
    conv1d3_f2<64, 128, 16><<<256, 256, SM_L5>>>(B, w5, A, 256, 64);
    // L6: A -> out [2,128,256,64]
    conv1d3_f2<128, 128, 16><<<256, 256, SM_L6>>>(A, w6, out, 256, 64);
}

// round 11
// speedup vs baseline: 1.5924x; 1.2079x over previous
#include <cuda_runtime.h>
#include <cuda_bf16.h>
#include <cstddef>
#include <cstdint>

// ---------------------------------------------------------------------------
// FrameLevelPartFeatureExtractor on GB300 — R6:
//  * pre-transposed weights [ci][k][co] (one-time tiny kernels)
//  * cp.async double-buffered weight chunks (overlap staging with compute)
//  * explicit next-tap weight-register prefetch inside fp32x2 inner loop
//  * L5/L6: 1-row 128-thread blocks (grid 512) for better SM fill
// ---------------------------------------------------------------------------

__device__ float g_bufA[2 * 32 * 1024 * 256];   // 64 MB scratch
__device__ float g_bufB[2 * 32 * 1024 * 256];   // 64 MB scratch

__device__ __align__(16) float g_wT2[32 * 9 * 32];
__device__ __align__(16) float g_wT3[32 * 9 * 64];
__device__ __align__(16) float g_wT4[64 * 9 * 64];
__device__ __align__(16) float g_wT5[64 * 3 * 128];
__device__ __align__(16) float g_wT6[128 * 3 * 128];

__device__ __forceinline__ float dleaky(float y) {
    // leaky_relu(leaky_relu(y, .01), .01) == y>=0 ? y : 1e-4*y
    return (y >= 0.f) ? y : 1e-4f * y;
}
__device__ __forceinline__ unsigned long long splat2(float v) {
    unsigned long long r;
    asm("mov.b64 %0, {%1, %1};" : "=l"(r) : "f"(v));
    return r;
}
__device__ __forceinline__ void fma2(unsigned long long& d,
                                     unsigned long long a,
                                     unsigned long long b) {
    asm("fma.rn.f32x2 %0, %1, %2, %3;" : "=l"(d) : "l"(a), "l"(b), "l"(d));
}
__device__ __forceinline__ void unpack2(float& lo, float& hi, unsigned long long v) {
    asm("mov.b64 {%0, %1}, %2;" : "=f"(lo), "=f"(hi) : "l"(v));
}
__device__ __forceinline__ void cp_async16(uint32_t dst, const void* src) {
    asm volatile("cp.async.ca.shared.global [%0], [%1], 16;"
                 :: "r"(dst), "l"(src));
}
__device__ __forceinline__ void cp_commit() {
    asm volatile("cp.async.commit_group;");
}
template <int N>
__device__ __forceinline__ void cp_wait() {
    asm volatile("cp.async.wait_group %0;" :: "n"(N));
}

// ---------------------------------------------------------------------------
// Weight transpose: wT[(ci*KK + kk)*COUT + co] = w[(co*CIN + ci)*9 + koff + kk]
// ---------------------------------------------------------------------------
__global__ __launch_bounds__(256)
void wtrans_k(const float* __restrict__ w, float* __restrict__ wT,
              int CIN, int COUT, int KK, int koff)
{
    int i = blockIdx.x * 256 + threadIdx.x;
    int total = CIN * KK * COUT;
    if (i >= total) return;
    int co = i % COUT;
    int r  = i / COUT;
    int kk = r % KK;
    int ci = r / KK;
    wT[i] = w[((size_t)co * CIN + ci) * 9 + koff + kk];
}

// ---------------------------------------------------------------------------
// L1: 5x5, CIN=1, COUT=32, pad 2, slice 512 (scalar; tiny layer)
// ---------------------------------------------------------------------------
__global__ __launch_bounds__(128, 4)
void conv5_l1(const float* __restrict__ in, const float* __restrict__ wt,
              float* __restrict__ out, int H, int W)
{
    constexpr int TH = 8, TW = 32, SR = TW + 5;
    constexpr int SLICE_H = 512, COUT = 32;
    __shared__ float sIn[(TH + 4) * SR];
    __shared__ float sWt[25 * COUT];

    const int b  = blockIdx.z;
    const int h0 = blockIdx.y * TH;
    const int w0 = blockIdx.x * TW;
    const int ss = (h0 / SLICE_H) * SLICE_H;
    const int se = ss + SLICE_H;
    const float* inb = in + (size_t)b * H * W;

    for (int i = threadIdx.x; i < (TH + 4) * (TW + 4); i += 128) {
        int c = i % (TW + 4), r = i / (TW + 4);
        int h = h0 - 2 + r, w = w0 - 2 + c;
        float v = 0.f;
        if (h >= ss && h < se && w >= 0 && w < W) v = inb[(size_t)h * W + w];
        sIn[r * SR + c] = v;
    }
    for (int i = threadIdx.x; i < 25 * COUT; i += 128) {
        int co = i % COUT, k = i / COUT;
        sWt[k * COUT + co] = wt[(size_t)co * 25 + k];
    }
    __syncthreads();

    const int t    = threadIdx.x;
    const int co0  = (t >> 5) * 8;
    const int pg   = t & 31;
    const int prow = pg >> 2;
    const int pc0  = (pg & 3) * 8;

    float acc[8][8];
#pragma unroll
    for (int i = 0; i < 8; ++i)
#pragma unroll
        for (int j = 0; j < 8; ++j) acc[i][j] = 0.f;

#pragma unroll
    for (int dy = 0; dy < 5; ++dy) {
#pragma unroll
        for (int dx = 0; dx < 5; ++dx) {
            const int k = dy * 5 + dx;
            const float4 wa = *(const float4*)(sWt + k * COUT + co0);
            const float4 wb = *(const float4*)(sWt + k * COUT + co0 + 4);
            const float wr[8] = {wa.x, wa.y, wa.z, wa.w, wb.x, wb.y, wb.z, wb.w};
            const float* ip = sIn + (prow + dy) * SR + pc0 + dx;
            float ir[8];
#pragma unroll
            for (int j = 0; j < 8; ++j) ir[j] = ip[j];
#pragma unroll
            for (int i = 0; i < 8; ++i)
#pragma unroll
                for (int j = 0; j < 8; ++j)
                    acc[i][j] = fmaf(wr[i], ir[j], acc[i][j]);
        }
    }

#pragma unroll
    for (int i = 0; i < 8; ++i) {
        float* op = out + (((size_t)b * COUT + co0 + i) * H + (h0 + prow)) * W + w0 + pc0;
#pragma unroll
        for (int j = 0; j < 8; ++j) op[j] = dleaky(acc[i][j]);
    }
}

// ---------------------------------------------------------------------------
// 3x3 conv, pad 1, slice-aware, fp32x2 co-pair packed.
// Weights pre-transposed [ci][k][co]; cp.async double-buffered chunks;
// next-tap weight registers prefetched.
// ---------------------------------------------------------------------------
template <int CIN, int COUT, int SLICE_H, int CICH>
__global__ __launch_bounds__((COUT / 8) * 32, (COUT == 32) ? 4 : 2)
void conv3x3_f2(const float* __restrict__ in, const float* __restrict__ wT,
                float* __restrict__ out, int H, int W)
{
    constexpr int TH = 8, TW = 32, SR = 36;      // rows 144B -> 16B aligned
    constexpr int NT = (COUT / 8) * 32;
    constexpr int IN_ELEMS = CIN * (TH + 2) * (TW + 2);
    constexpr int CHW = CICH * 9 * COUT;          // floats per weight chunk

    extern __shared__ float smem[];
    float* sIn = smem;                              // CIN*(TH+2)*SR
    float* sWt = smem + CIN * (TH + 2) * SR;        // 2*CHW (double buffer)
    const uint32_t sWtBase =
        (uint32_t)__cvta_generic_to_shared(sWt);

    const int b  = blockIdx.z;
    const int h0 = blockIdx.y * TH;
    const int w0 = blockIdx.x * TW;
    const int ss = (h0 / SLICE_H) * SLICE_H;
    const int se = ss + SLICE_H;
    const float* inb = in + (size_t)b * CIN * H * W;

    // stage chunk 0 weights (async) before the input loads
    {
        const float* src = wT;
        for (int i = threadIdx.x * 4; i < CHW; i += NT * 4)
            cp_async16(sWtBase + (uint32_t)i * 4u, src + i);
        cp_commit();
    }

    for (int i = threadIdx.x; i < IN_ELEMS; i += NT) {
        int c  = i % (TW + 2);
        int r  = (i / (TW + 2)) % (TH + 2);
        int ci = i / ((TW + 2) * (TH + 2));
        int h = h0 - 1 + r;
        int w = w0 - 1 + c;
        float v = 0.f;
        if (h >= ss && h < se && w >= 0 && w < W)
            v = inb[((size_t)ci * H + h) * W + w];
        sIn[(ci * (TH + 2) + r) * SR + c] = v;
    }

    const int t    = threadIdx.x;
    const int co0  = (t >> 5) * 8;
    const int pg   = t & 31;
    const int prow = pg >> 2;
    const int pc0  = (pg & 3) * 8;

    unsigned long long acc[4][8];
#pragma unroll
    for (int i = 0; i < 4; ++i)
#pragma unroll
        for (int j = 0; j < 8; ++j) acc[i][j] = 0ull;

    int pb = 0;
    for (int cc = 0; cc < CIN; cc += CICH) {
        if (cc + CICH < CIN) {
            const float* src = wT + (size_t)(cc + CICH) * 9 * COUT;
            uint32_t dst = sWtBase + (uint32_t)((pb ^ 1) * CHW) * 4u;
            for (int i = t * 4; i < CHW; i += NT * 4)
                cp_async16(dst + (uint32_t)i * 4u, src + i);
            cp_commit();
            cp_wait<1>();
        } else {
            cp_wait<0>();
        }
        __syncthreads();
        const float* bufp = sWt + pb * CHW;

#pragma unroll 1
        for (int cil = 0; cil < CICH; ++cil) {
            const float* sInC = sIn + (size_t)(cc + cil) * (TH + 2) * SR;
            const float* sWk  = bufp + cil * 9 * COUT;
            ulonglong2 cwA = *(const ulonglong2*)(sWk + co0);
            ulonglong2 cwB = *(const ulonglong2*)(sWk + co0 + 4);
#pragma unroll
            for (int dy = 0; dy < 3; ++dy) {
                const float* rp = sInC + (prow + dy) * SR + pc0;
                const float4 ra = *(const float4*)(rp);
                const float4 rb = *(const float4*)(rp + 4);
                const float4 rc = *(const float4*)(rp + 8);
                unsigned long long s[10];
                s[0] = splat2(ra.x); s[1] = splat2(ra.y);
                s[2] = splat2(ra.z); s[3] = splat2(ra.w);
                s[4] = splat2(rb.x); s[5] = splat2(rb.y);
                s[6] = splat2(rb.z); s[7] = splat2(rb.w);
                s[8] = splat2(rc.x); s[9] = splat2(rc.y);
#pragma unroll
                for (int dx = 0; dx < 3; ++dx) {
                    const int k = dy * 3 + dx;
                    ulonglong2 nwA = cwA, nwB = cwB;
                    if (k < 8) {
                        nwA = *(const ulonglong2*)(sWk + (k + 1) * COUT + co0);
                        nwB = *(const ulonglong2*)(sWk + (k + 1) * COUT + co0 + 4);
                    }
#pragma unroll
                    for (int j = 0; j < 8; ++j) {
                        fma2(acc[0][j], cwA.x, s[dx + j]);
                        fma2(acc[1][j], cwA.y, s[dx + j]);
                        fma2(acc[2][j], cwB.x, s[dx + j]);
                        fma2(acc[3][j], cwB.y, s[dx + j]);
                    }
                    cwA = nwA; cwB = nwB;
                }
            }
        }
        __syncthreads();   // all reads of bufp done before it is restaged
        pb ^= 1;
    }

#pragma unroll
    for (int i = 0; i < 4; ++i) {
        float* opL = out + (((size_t)b * COUT + co0 + 2 * i) * H + (h0 + prow)) * W + w0 + pc0;
        float* opH = opL + (size_t)H * W;
#pragma unroll
        for (int j = 0; j < 8; ++j) {
            float lo, hi;
            unpack2(lo, hi, acc[i][j]);
            opL[j] = dleaky(lo);
            opH[j] = dleaky(hi);
        }
    }
}

// ---------------------------------------------------------------------------
// 1-D conv (3 taps, middle kernel row), per-row, W=64, pad 1, fp32x2 packed.
// 1 row per 128-thread block (grid = B*H = 512). Weights pre-transposed
// [ci][dx][co]; cp.async double-buffered; next-tap weight prefetch.
// ---------------------------------------------------------------------------
template <int CIN, int COUT, int CICH>
__global__ __launch_bounds__(128, 4)
void conv1d3_f2(const float* __restrict__ in, const float* __restrict__ wT,
                float* __restrict__ out, int H, int W)
{
    constexpr int SR = 68;   // 272B rows -> 16B aligned
    constexpr int NT = 128;
    constexpr int CHW = CICH * 3 * COUT;

    extern __shared__ float smem[];
    float* sIn = smem;                   // CIN*SR
    float* sWt = smem + CIN * SR;        // 2*CHW
    const uint32_t sWtBase =
        (uint32_t)__cvta_generic_to_shared(sWt);

    const int R = blockIdx.x;
    const int b = R / H, h = R % H;

    // stage chunk 0 weights (async)
    {
        for (int i = threadIdx.x * 4; i < CHW; i += NT * 4)
            cp_async16(sWtBase + (uint32_t)i * 4u, wT + i);
        cp_commit();
    }

    for (int i = threadIdx.x; i < CIN * (W + 2); i += NT) {
        int c  = i % (W + 2);
        int ci = i / (W + 2);
        int w = c - 1;
        float v = 0.f;
        if (w >= 0 && w < W)
            v = in[(((size_t)b * CIN + ci) * H + h) * W + w];
        sIn[ci * SR + c] = v;
    }

    const int t    = threadIdx.x;
    const int co0  = (t >> 3) * 8;     // 16 co-groups of 8
    const int pc0  = (t & 7) * 8;      // 8 px-groups of 8

    unsigned long long acc[4][8];
#pragma unroll
    for (int i = 0; i < 4; ++i)
#pragma unroll
        for (int j = 0; j < 8; ++j) acc[i][j] = 0ull;

    int pb = 0;
    for (int cc = 0; cc < CIN; cc += CICH) {
        if (cc + CICH < CIN) {
            const float* src = wT + (size_t)(cc + CICH) * 3 * COUT;
            uint32_t dst = sWtBase + (uint32_t)((pb ^ 1) * CHW) * 4u;
            for (int i = t * 4; i < CHW; i += NT * 4)
                cp_async16(dst + (uint32_t)i * 4u, src + i);
            cp_commit();
            cp_wait<1>();
        } else {
            cp_wait<0>();
        }
        __syncthreads();
        const float* bufp = sWt + pb * CHW;

#pragma unroll 1
        for (int cil = 0; cil < CICH; ++cil) {
            const float* rp  = sIn + (size_t)(cc + cil) * SR + pc0;
            const float* sWk = bufp + cil * 3 * COUT;
            const float4 ra = *(const float4*)(rp);
            const float4 rb = *(const float4*)(rp + 4);
            const float4 rc = *(const float4*)(rp + 8);
            unsigned long long s[10];
            s[0] = splat2(ra.x); s[1] = splat2(ra.y);
            s[2] = splat2(ra.z); s[3] = splat2(ra.w);
            s[4] = splat2(rb.x); s[5] = splat2(rb.y);
            s[6] = splat2(rb.z); s[7] = splat2(rb.w);
            s[8] = splat2(rc.x); s[9] = splat2(rc.y);
            ulonglong2 cwA = *(const ulonglong2*)(sWk + co0);
            ulonglong2 cwB = *(const ulonglong2*)(sWk + co0 + 4);
#pragma unroll
            for (int dx = 0; dx < 3; ++dx) {
                ulonglong2 nwA = cwA, nwB = cwB;
                if (dx < 2) {
                    nwA = *(const ulonglong2*)(sWk + (dx + 1) * COUT + co0);
                    nwB = *(const ulonglong2*)(sWk + (dx + 1) * COUT + co0 + 4);
                }
#pragma unroll
                for (int j = 0; j < 8; ++j) {
                    fma2(acc[0][j], cwA.x, s[dx + j]);
                    fma2(acc[1][j], cwA.y, s[dx + j]);
                    fma2(acc[2][j], cwB.x, s[dx + j]);
                    fma2(acc[3][j], cwB.y, s[dx + j]);
                }
                cwA = nwA; cwB = nwB;
            }
        }
        __syncthreads();
        pb ^= 1;
    }

#pragma unroll
    for (int i = 0; i < 4; ++i) {
        float* opL = out + (((size_t)b * COUT + co0 + 2 * i) * H + h) * W + pc0;
        float* opH = opL + (size_t)H * W;
#pragma unroll
        for (int j = 0; j < 8; ++j) {
            float lo, hi;
            unpack2(lo, hi, acc[i][j]);
            opL[j] = dleaky(lo);
            opH[j] = dleaky(hi);
        }
    }
}

// ---------------------------------------------------------------------------
// 2x2 max pool, stride 2
// ---------------------------------------------------------------------------
__global__ __launch_bounds__(256)
void maxpool2_k(const float* __restrict__ in, float* __restrict__ out,
                int BC, int H2, int W2)
{
    int idx = blockIdx.x * blockDim.x + threadIdx.x;
    int N = BC * H2 * W2;
    if (idx >= N) return;
    int wo = idx % W2;
    int ho = (idx / W2) % H2;
    int bc = idx / (W2 * H2);
    const float* p = in + (((size_t)bc * (2 * H2)) + 2 * ho) * (2 * W2) + 2 * wo;
    float m0 = fmaxf(p[0], p[1]);
    float m1 = fmaxf(p[2 * W2], p[2 * W2 + 1]);
    out[idx] = fmaxf(m0, m1);
}

// ---------------------------------------------------------------------------
// Host launcher
//   smem (input + 2x weight chunk), CTAs/SM:
//   L2 CICH4: 55.3KB x4   L3 CICH8: 82.9KB x2   L4 CICH4: 110.6KB x2
//   L5 CICH8: 42.0KB x4   L6 CICH4: 47.1KB x4
// ---------------------------------------------------------------------------
static constexpr int SM_L2 = (32 * 10 * 36 + 2 * 4 * 9 * 32) * 4;    //  55,296
static constexpr int SM_L3 = (32 * 10 * 36 + 2 * 8 * 9 * 64) * 4;    //  82,944
static constexpr int SM_L4 = (64 * 10 * 36 + 2 * 4 * 9 * 64) * 4;    // 110,592
static constexpr int SM_L5 = (64 * 68 + 2 * 8 * 3 * 128) * 4;        //  41,984
static constexpr int SM_L6 = (128 * 68 + 2 * 4 * 3 * 128) * 4;       //  47,104

extern "C" void kernel_launch(void* const* d_in, const int* in_sizes, int n_in,
                              void* d_out, int out_size)
{
    const float* x  = (const float*)d_in[0];
    const float* w1 = (const float*)d_in[1];
    const float* w2 = (const float*)d_in[2];
    const float* w3 = (const float*)d_in[3];
    const float* w4 = (const float*)d_in[4];
    const float* w5 = (const float*)d_in[5];
    const float* w6 = (const float*)d_in[6];
    float* out = (float*)d_out;

    float *A, *B, *T2, *T3, *T4, *T5, *T6;
    cudaGetSymbolAddress((void**)&A, g_bufA);
    cudaGetSymbolAddress((void**)&B, g_bufB);
    cudaGetSymbolAddress((void**)&T2, g_wT2);
    cudaGetSymbolAddress((void**)&T3, g_wT3);
    cudaGetSymbolAddress((void**)&T4, g_wT4);
    cudaGetSymbolAddress((void**)&T5, g_wT5);
    cudaGetSymbolAddress((void**)&T6, g_wT6);

    cudaFuncSetAttribute(conv3x3_f2<32, 32, 512, 4>,
                         cudaFuncAttributeMaxDynamicSharedMemorySize, SM_L2);
    cudaFuncSetAttribute(conv3x3_f2<32, 64, 32, 8>,
                         cudaFuncAttributeMaxDynamicSharedMemorySize, SM_L3);
    cudaFuncSetAttribute(conv3x3_f2<64, 64, 32, 4>,
                         cudaFuncAttributeMaxDynamicSharedMemorySize, SM_L4);
    cudaFuncSetAttribute(conv1d3_f2<64, 128, 8>,
                         cudaFuncAttributeMaxDynamicSharedMemorySize, SM_L5);
    cudaFuncSetAttribute(conv1d3_f2<128, 128, 4>,
                         cudaFuncAttributeMaxDynamicSharedMemorySize, SM_L6);

    // weight transposes (one-time, tiny)
    wtrans_k<<<(32 * 9 * 32 + 255) / 256, 256>>>(w2, T2, 32, 32, 9, 0);
    wtrans_k<<<(32 * 9 * 64 + 255) / 256, 256>>>(w3, T3, 32, 64, 9, 0);
    wtrans_k<<<(64 * 9 * 64 + 255) / 256, 256>>>(w4, T4, 64, 64, 9, 0);
    wtrans_k<<<(64 * 3 * 128 + 255) / 256, 256>>>(w5, T5, 64, 128, 3, 3);
    wtrans_k<<<(128 * 3 * 128 + 255) / 256, 256>>>(w6, T6, 128, 128, 3, 3);

    // L1: x [2,1,1024,256] -> A [2,32,1024,256]
    conv5_l1<<<dim3(8, 128, 2), 128>>>(x, w1, A, 1024, 256);
    // L2: A -> B [2,32,1024,256]
    conv3x3_f2<32, 32, 512, 4><<<dim3(8, 128, 2), 128, SM_L2>>>(A, T2, B, 1024, 256);
    // P1: B -> A [2,32,512,128]
    maxpool2_k<<<(2 * 32 * 512 * 128 + 255) / 256, 256>>>(B, A, 64, 512, 128);
    // L3: A -> B [2,64,512,128]
    conv3x3_f2<32, 64, 32, 8><<<dim3(4, 64, 2), 256, SM_L3>>>(A, T3, B, 512, 128);
    // L4: B -> A [2,64,512,128]
    conv3x3_f2<64, 64, 32, 4><<<dim3(4, 64, 2), 256, SM_L4>>>(B, T4, A, 512, 128);
    // P2: A -> B [2,64,256,64]
    maxpool2_k<<<(2 * 64 * 256 * 64 + 255) / 256, 256>>>(A, B, 128, 256, 64);
    // L5: B -> A [2,128,256,64]
    conv1d3_f2<64, 128, 8><<<512, 128, SM_L5>>>(B, T5, A, 256, 64);
    // L6: A -> out [2,128,256,64]
    conv1d3_f2<128, 128, 4><<<512, 128, SM_L6>>>(A, T6, out, 256, 64);
}